// round 6
// baseline (speedup 1.0000x reference)
#include <cuda_runtime.h>
#include <cuda_fp16.h>
#include <cstdint>

// out = tanh(x @ W^T + b); x (131072, 256) fp32, W (256,256) fp32, b (256).
//
// mma.sync m16n8k16 f16->f32 (compute_103-portable). Round-6: occupancy
// restructure. 512 threads / 16 warps; warp (p = w&7, h = w>>3) owns
// n-slice [p*32, p*32+32) x K-half [h*128, h*128+128): W = 64 regs,
// MT = 32 tokens -> acc = 32 regs -> ~124 regs/thread -> 4 warps/SMSP.
// K-split partials combined via lane-aligned SMEM exchange (frag layouts
// identical across the pair -> no transpose) + named barrier per pair;
// each warp epilogues half the tokens. cp.async double stage + fp16
// double buffer + swizzles unchanged from the proven r5 kernel.

#define HID      256
#define MT       32
#define NT       4096          // 131072 / 32
#define GRID     148
#define NTHREADS 512

// SMEM (bytes): 2 fp32 stages (32KB), 2 fp16 bufs (16KB), 8 pair-scratch (4KB)
#define SM_S0    0u
#define SM_S1    32768u
#define SM_B0    65536u
#define SM_B1    81920u
#define SM_SCR   98304u
#define SMEM_TOTAL 131072

// ---------------------------------------------------------------- helpers ----

__device__ __forceinline__ uint32_t smem_u32(const void* p) {
    uint32_t a;
    asm("{ .reg .u64 t; cvta.to.shared.u64 t, %1; cvt.u32.u64 %0, t; }"
        : "=r"(a) : "l"(p));
    return a;
}

__device__ __forceinline__ void cp_async16(uint32_t dst, const void* src) {
    asm volatile("cp.async.cg.shared.global [%0], [%1], 16;"
                 :: "r"(dst), "l"(src) : "memory");
}
__device__ __forceinline__ void cp_commit() {
    asm volatile("cp.async.commit_group;" ::: "memory");
}
__device__ __forceinline__ void cp_wait0() {
    asm volatile("cp.async.wait_group 0;" ::: "memory");
}
__device__ __forceinline__ void cp_wait1() {
    asm volatile("cp.async.wait_group 1;" ::: "memory");
}

__device__ __forceinline__ void sts64(uint32_t addr, uint32_t a, uint32_t b) {
    asm volatile("st.shared.v2.u32 [%0], {%1, %2};" :: "r"(addr), "r"(a), "r"(b));
}
__device__ __forceinline__ void sts128f(uint32_t addr, const float* v) {
    asm volatile("st.shared.v4.f32 [%0], {%1, %2, %3, %4};"
                 :: "r"(addr), "f"(v[0]), "f"(v[1]), "f"(v[2]), "f"(v[3]));
}
__device__ __forceinline__ void lds128f(float* v, uint32_t addr) {
    asm volatile("ld.shared.v4.f32 {%0, %1, %2, %3}, [%4];"
                 : "=f"(v[0]), "=f"(v[1]), "=f"(v[2]), "=f"(v[3]) : "r"(addr));
}
__device__ __forceinline__ void lds128(uint32_t* r, uint32_t addr) {
    asm volatile("ld.shared.v4.u32 {%0, %1, %2, %3}, [%4];"
                 : "=r"(r[0]), "=r"(r[1]), "=r"(r[2]), "=r"(r[3]) : "r"(addr));
}

__device__ __forceinline__ void ldsm_x4(uint32_t* r, uint32_t addr) {
    asm volatile("ldmatrix.sync.aligned.m8n8.x4.shared.b16 {%0, %1, %2, %3}, [%4];"
                 : "=r"(r[0]), "=r"(r[1]), "=r"(r[2]), "=r"(r[3]) : "r"(addr));
}

__device__ __forceinline__ void mma16816(float* d, const uint32_t* a,
                                         const uint32_t* bfr) {
    asm volatile(
        "mma.sync.aligned.m16n8k16.row.col.f32.f16.f16.f32 "
        "{%0, %1, %2, %3}, {%4, %5, %6, %7}, {%8, %9}, {%0, %1, %2, %3};"
        : "+f"(d[0]), "+f"(d[1]), "+f"(d[2]), "+f"(d[3])
        : "r"(a[0]), "r"(a[1]), "r"(a[2]), "r"(a[3]), "r"(bfr[0]), "r"(bfr[1]));
}

__device__ __forceinline__ float tanh_f(float y) {
    float r;
    asm("tanh.approx.f32 %0, %1;" : "=f"(r) : "f"(y));
    return r;
}

__device__ __forceinline__ void bar_pair(int id) {
    asm volatile("bar.sync %0, 64;" :: "r"(id) : "memory");
}

// coalesced cp.async of one 32-token fp32 tile (32KB) into a stage
__device__ __forceinline__ void fill_stage(const float* __restrict__ x, int t,
                                           uint32_t stage, int tid) {
#pragma unroll
    for (int i = 0; i < 4; i++) {
        int g = tid + i * NTHREADS;            // 0..2047 16B chunks
        cp_async16(stage + (uint32_t)g * 16u,
                   (const char*)(x + (size_t)t * MT * HID) + (size_t)g * 16);
    }
}

// fp32 stage -> fp16 buffer (ldmatrix-swizzled: 32 rows x 512B)
__device__ __forceinline__ void convert_tile(uint32_t src, uint32_t dst, int tid) {
#pragma unroll
    for (int i = 0; i < 4; i++) {
        int g = tid + i * NTHREADS;            // float4 index, row-major
        uint32_t r[4];
        lds128(r, src + (uint32_t)g * 16u);
        __half2 h0 = __floats2half2_rn(__uint_as_float(r[0]), __uint_as_float(r[1]));
        __half2 h1 = __floats2half2_rn(__uint_as_float(r[2]), __uint_as_float(r[3]));
        uint32_t row = (uint32_t)(g >> 6);     // 64 float4 per row
        uint32_t c4  = (uint32_t)(g & 63);
        uint32_t c16 = c4 >> 1;
        uint32_t a = dst + row * 512u + ((c16 ^ (row & 7u)) << 4) + (c4 & 1u) * 8u;
        sts64(a, *(const uint32_t*)&h0, *(const uint32_t*)&h1);
    }
}

// ----------------------------------------------------------------- kernel ----

__global__ void __launch_bounds__(NTHREADS, 1)
rotor_kernel(const float* __restrict__ x, const float* __restrict__ W,
             const float* __restrict__ b, float* __restrict__ out) {
    extern __shared__ char smem[];
    const uint32_t sb = smem_u32(smem);
    const int tid = threadIdx.x;
    const int w = tid >> 5;
    const int l = tid & 31;
    const int p = w & 7;       // n-slice id (pair id)
    const int h = w >> 3;      // K-half

    const int t0 = blockIdx.x;

    // --- two fills in flight before anything waits
    fill_stage(x, t0, sb + SM_S0, tid);
    cp_commit();
    fill_stage(x, t0 + GRID, sb + SM_S1, tid);   // t0+GRID < NT always (295<4096)
    cp_commit();

    // --- W -> registers (under fill latency). Warp covers n in
    // [p*32, p*32+32), k in [h*128, h*128+128). B frag (m16n8k16 col):
    //   b0={W[n][k],W[n][k+1]}, b1={W[n][k+8],W[n][k+9]},
    //   n = p*32+na*8+(l>>2), k = h*128+ks*16+(l&3)*2.
    uint32_t wreg[4][8][2];
    {
        const float2* Wv = (const float2*)W;
        const int nb = p * 32 + (l >> 2);
        const int kb = h * 128 + (l & 3) * 2;
#pragma unroll
        for (int na = 0; na < 4; na++) {
            const int n = nb + na * 8;
#pragma unroll
            for (int ks = 0; ks < 8; ks++) {
                const int k = kb + ks * 16;
                float2 f0 = Wv[n * 128 + (k >> 1)];
                float2 f1 = Wv[n * 128 + ((k + 8) >> 1)];
                __half2 h0 = __floats2half2_rn(f0.x, f0.y);
                __half2 h1 = __floats2half2_rn(f1.x, f1.y);
                wreg[na][ks][0] = *(const uint32_t*)&h0;
                wreg[na][ks][1] = *(const uint32_t*)&h1;
            }
        }
    }
    float2 bb[4];
#pragma unroll
    for (int na = 0; na < 4; na++)
        bb[na] = *(const float2*)&b[p * 32 + na * 8 + (l & 3) * 2];

    // pair scratch: region[d] holds partials for epilogue-half d; pure
    // lane-aligned exchange (both warps share the same frag layout).
    const uint32_t scr = sb + SM_SCR + (uint32_t)p * 4096u + (uint32_t)l * 64u;

    // --- convert tile t0 (own chunks only -> cp_wait1 suffices)
    cp_wait1();
    convert_tile(sb + SM_S0, sb + SM_B0, tid);

    int iter = 0;
    for (int t = t0; t < NT; t += GRID, iter++) {
        const uint32_t bufg = sb + ((iter & 1) ? SM_B1 : SM_B0);   // GEMM src
        const uint32_t bufc = sb + ((iter & 1) ? SM_B0 : SM_B1);   // convert dst
        const uint32_t stf  = sb + ((iter & 1) ? SM_S1 : SM_S0);   // fill dst
        const uint32_t stc  = sb + ((iter & 1) ? SM_S0 : SM_S1);   // convert src
        const bool have_next = (t + GRID) < NT;

        cp_wait0();          // fill(t+1) arrived (committed one iter ago)
        __syncthreads();     // orders buffer reuse + cp.async visibility

        if (t + 2 * GRID < NT) fill_stage(x, t + 2 * GRID, stf, tid);
        cp_commit();
        if (have_next) convert_tile(stc, bufc, tid);

        // --- GEMM: this warp: m 0..31 x n-slice 32 x its K-half
        float acc[2][4][4];
#pragma unroll
        for (int ma = 0; ma < 2; ma++)
#pragma unroll
            for (int na = 0; na < 4; na++)
#pragma unroll
                for (int c = 0; c < 4; c++) acc[ma][na][c] = 0.0f;

#pragma unroll
        for (int ks = 0; ks < 8; ks++) {
            uint32_t af[2][4];
#pragma unroll
            for (int ma = 0; ma < 2; ma++) {
                const uint32_t row = (uint32_t)(ma * 16 + (l & 15));
                const uint32_t c16 = (uint32_t)(h * 16 + ks * 2 + (l >> 4));
                ldsm_x4(af[ma], bufg + row * 512u + ((c16 ^ (row & 7u)) << 4));
            }
#pragma unroll
            for (int ma = 0; ma < 2; ma++)
#pragma unroll
                for (int na = 0; na < 4; na++)
                    mma16816(acc[ma][na], af[ma], wreg[na][ks]);
        }

        // --- K-split reduction: write acc[1-h] to region[1-h], read region[h]
        {
            const uint32_t so = scr + (uint32_t)(1 - h) * 2048u;
#pragma unroll
            for (int na = 0; na < 4; na++)
                sts128f(so + (uint32_t)na * 16u, acc[1 - h][na]);
        }
        bar_pair(p + 1);

        // --- epilogue for tokens [h*16, h*16+16)
        const int m0 = t * MT + h * 16;
        const uint32_t si = scr + (uint32_t)h * 2048u;
#pragma unroll
        for (int na = 0; na < 4; na++) {
            float part[4];
            lds128f(part, si + (uint32_t)na * 16u);
            const int n = p * 32 + na * 8 + (l & 3) * 2;
            float2 v0, v1;
            v0.x = tanh_f(acc[h][na][0] + part[0] + bb[na].x);
            v0.y = tanh_f(acc[h][na][1] + part[1] + bb[na].y);
            v1.x = tanh_f(acc[h][na][2] + part[2] + bb[na].x);
            v1.y = tanh_f(acc[h][na][3] + part[3] + bb[na].y);
            const int r0 = m0 + (l >> 2);
            __stcs((float2*)&out[(size_t)r0 * HID + n], v0);
            __stcs((float2*)&out[(size_t)(r0 + 8) * HID + n], v1);
        }
    }
}

// ----------------------------------------------------------------- launch ----

extern "C" void kernel_launch(void* const* d_in, const int* in_sizes, int n_in,
                              void* d_out, int out_size) {
    const float* x = (const float*)d_in[0];
    const float* W = (const float*)d_in[1];
    const float* b = (const float*)d_in[2];
    float* out = (float*)d_out;
    cudaFuncSetAttribute(rotor_kernel,
                         cudaFuncAttributeMaxDynamicSharedMemorySize, SMEM_TOTAL);
    rotor_kernel<<<GRID, NTHREADS, SMEM_TOTAL>>>(x, W, b, out);
}

// round 7
// speedup vs baseline: 1.3987x; 1.3987x over previous
#include <cuda_runtime.h>
#include <cuda_fp16.h>
#include <cstdint>

// out = tanh(x @ W^T + b); x (131072, 256) fp32, W (256,256) fp32, b (256).
//
// mma.sync m16n8k16 f16->f32 (compute_103-portable). 512 threads / 16 warps;
// warp (p = w&7, h = w>>3) owns n-slice [p*32,p*32+32) x K-half
// [h*128,h*128+128): W = 64 regs, acc = 32 regs -> ~128 regs -> 4 warps/SMSP.
//
// Round-7 fixes vs r6 (which hit a 16-way bank conflict in the K-split
// exchange, doubling L1-busy):
//   - exchange scratch is token-major, 16B-chunk XOR-swizzled: conflict-free.
//   - scratch doubles as a store bounce: both halves' partials go to SMEM,
//     each warp reads+sums its 16-token half and emits fully-coalesced
//     4x128B STG.128 (no more 32B-segment scattered stores).

#define HID      256
#define MT       32
#define NT       4096
#define GRID     148
#define NTHREADS 512

// SMEM (bytes): 2 fp32 stages (32KB ea), 2 fp16 bufs (16KB ea),
// exchange scratch 8 pairs x 8KB = 64KB.
#define SM_S0    0u
#define SM_S1    32768u
#define SM_B0    65536u
#define SM_B1    81920u
#define SM_SCR   98304u
#define SMEM_TOTAL (98304 + 65536)

// ---------------------------------------------------------------- helpers ----

__device__ __forceinline__ uint32_t smem_u32(const void* p) {
    uint32_t a;
    asm("{ .reg .u64 t; cvta.to.shared.u64 t, %1; cvt.u32.u64 %0, t; }"
        : "=r"(a) : "l"(p));
    return a;
}

__device__ __forceinline__ void cp_async16(uint32_t dst, const void* src) {
    asm volatile("cp.async.cg.shared.global [%0], [%1], 16;"
                 :: "r"(dst), "l"(src) : "memory");
}
__device__ __forceinline__ void cp_commit() {
    asm volatile("cp.async.commit_group;" ::: "memory");
}
__device__ __forceinline__ void cp_wait0() {
    asm volatile("cp.async.wait_group 0;" ::: "memory");
}
__device__ __forceinline__ void cp_wait1() {
    asm volatile("cp.async.wait_group 1;" ::: "memory");
}

__device__ __forceinline__ void sts64(uint32_t addr, uint32_t a, uint32_t b) {
    asm volatile("st.shared.v2.u32 [%0], {%1, %2};" :: "r"(addr), "r"(a), "r"(b));
}
__device__ __forceinline__ void sts64f(uint32_t addr, float a, float b) {
    asm volatile("st.shared.v2.f32 [%0], {%1, %2};" :: "r"(addr), "f"(a), "f"(b));
}
__device__ __forceinline__ void lds128f(float* v, uint32_t addr) {
    asm volatile("ld.shared.v4.f32 {%0, %1, %2, %3}, [%4];"
                 : "=f"(v[0]), "=f"(v[1]), "=f"(v[2]), "=f"(v[3]) : "r"(addr));
}
__device__ __forceinline__ void lds128(uint32_t* r, uint32_t addr) {
    asm volatile("ld.shared.v4.u32 {%0, %1, %2, %3}, [%4];"
                 : "=r"(r[0]), "=r"(r[1]), "=r"(r[2]), "=r"(r[3]) : "r"(addr));
}

__device__ __forceinline__ void ldsm_x4(uint32_t* r, uint32_t addr) {
    asm volatile("ldmatrix.sync.aligned.m8n8.x4.shared.b16 {%0, %1, %2, %3}, [%4];"
                 : "=r"(r[0]), "=r"(r[1]), "=r"(r[2]), "=r"(r[3]) : "r"(addr));
}

__device__ __forceinline__ void mma16816(float* d, const uint32_t* a,
                                         const uint32_t* bfr) {
    asm volatile(
        "mma.sync.aligned.m16n8k16.row.col.f32.f16.f16.f32 "
        "{%0, %1, %2, %3}, {%4, %5, %6, %7}, {%8, %9}, {%0, %1, %2, %3};"
        : "+f"(d[0]), "+f"(d[1]), "+f"(d[2]), "+f"(d[3])
        : "r"(a[0]), "r"(a[1]), "r"(a[2]), "r"(a[3]), "r"(bfr[0]), "r"(bfr[1]));
}

__device__ __forceinline__ float tanh_f(float y) {
    float r;
    asm("tanh.approx.f32 %0, %1;" : "=f"(r) : "f"(y));
    return r;
}

__device__ __forceinline__ void bar_pair(int id) {
    asm volatile("bar.sync %0, 64;" :: "r"(id) : "memory");
}

// coalesced cp.async of one 32-token fp32 tile (32KB) into a stage
__device__ __forceinline__ void fill_stage(const float* __restrict__ x, int t,
                                           uint32_t stage, int tid) {
#pragma unroll
    for (int i = 0; i < 4; i++) {
        int g = tid + i * NTHREADS;
        cp_async16(stage + (uint32_t)g * 16u,
                   (const char*)(x + (size_t)t * MT * HID) + (size_t)g * 16);
    }
}

// fp32 stage -> fp16 buffer (ldmatrix-swizzled: 32 rows x 512B)
__device__ __forceinline__ void convert_tile(uint32_t src, uint32_t dst, int tid) {
#pragma unroll
    for (int i = 0; i < 4; i++) {
        int g = tid + i * NTHREADS;
        uint32_t r[4];
        lds128(r, src + (uint32_t)g * 16u);
        __half2 h0 = __floats2half2_rn(__uint_as_float(r[0]), __uint_as_float(r[1]));
        __half2 h1 = __floats2half2_rn(__uint_as_float(r[2]), __uint_as_float(r[3]));
        uint32_t row = (uint32_t)(g >> 6);
        uint32_t c4  = (uint32_t)(g & 63);
        uint32_t c16 = c4 >> 1;
        uint32_t a = dst + row * 512u + ((c16 ^ (row & 7u)) << 4) + (c4 & 1u) * 8u;
        sts64(a, *(const uint32_t*)&h0, *(const uint32_t*)&h1);
    }
}

// ----------------------------------------------------------------- kernel ----

__global__ void __launch_bounds__(NTHREADS, 1)
rotor_kernel(const float* __restrict__ x, const float* __restrict__ W,
             const float* __restrict__ b, float* __restrict__ out) {
    extern __shared__ char smem[];
    const uint32_t sb = smem_u32(smem);
    const int tid = threadIdx.x;
    const int w = tid >> 5;
    const int l = tid & 31;
    const int p = w & 7;       // n-slice / pair id
    const int h = w >> 3;      // K-half

    const int t0 = blockIdx.x;

    // --- two fills in flight before anything waits
    fill_stage(x, t0, sb + SM_S0, tid);
    cp_commit();
    fill_stage(x, t0 + GRID, sb + SM_S1, tid);   // t0+GRID < NT always
    cp_commit();

    // --- W -> registers (under fill latency). Warp covers n in
    // [p*32,p*32+32), k in [h*128,h*128+128). B frag (m16n8k16 col):
    //   n = p*32+na*8+(l>>2), k = h*128+ks*16+(l&3)*2.
    uint32_t wreg[4][8][2];
    {
        const float2* Wv = (const float2*)W;
        const int nb = p * 32 + (l >> 2);
        const int kb = h * 128 + (l & 3) * 2;
#pragma unroll
        for (int na = 0; na < 4; na++) {
            const int n = nb + na * 8;
#pragma unroll
            for (int ks = 0; ks < 8; ks++) {
                const int k = kb + ks * 16;
                float2 f0 = Wv[n * 128 + (k >> 1)];
                float2 f1 = Wv[n * 128 + ((k + 8) >> 1)];
                __half2 h0 = __floats2half2_rn(f0.x, f0.y);
                __half2 h1 = __floats2half2_rn(f1.x, f1.y);
                wreg[na][ks][0] = *(const uint32_t*)&h0;
                wreg[na][ks][1] = *(const uint32_t*)&h1;
            }
        }
    }
    // bias for this thread's coalesced epilogue columns
    const float4 b4 = *(const float4*)&b[p * 32 + (l & 7) * 4];

    // pair scratch: token-major, sub-region per K-half; 16B-chunk XOR swizzle.
    const uint32_t scrp = sb + SM_SCR + (uint32_t)p * 8192u;

    // --- convert tile t0 (own chunks only -> cp_wait1 suffices)
    cp_wait1();
    convert_tile(sb + SM_S0, sb + SM_B0, tid);

    int iter = 0;
    for (int t = t0; t < NT; t += GRID, iter++) {
        const uint32_t bufg = sb + ((iter & 1) ? SM_B1 : SM_B0);   // GEMM src
        const uint32_t bufc = sb + ((iter & 1) ? SM_B0 : SM_B1);   // convert dst
        const uint32_t stf  = sb + ((iter & 1) ? SM_S1 : SM_S0);   // fill dst
        const uint32_t stc  = sb + ((iter & 1) ? SM_S0 : SM_S1);   // convert src
        const bool have_next = (t + GRID) < NT;

        cp_wait0();          // fill(t+1) arrived (committed one iter ago)
        // Orders: buffer reuse, cp.async visibility, and ALL reads of the
        // exchange scratch from the previous iteration (so writes below race
        // with nothing).
        __syncthreads();

        if (t + 2 * GRID < NT) fill_stage(x, t + 2 * GRID, stf, tid);
        cp_commit();
        if (have_next) convert_tile(stc, bufc, tid);

        // --- GEMM: m 0..31 x n-slice 32 x this warp's K-half
        float acc[2][4][4];
#pragma unroll
        for (int ma = 0; ma < 2; ma++)
#pragma unroll
            for (int na = 0; na < 4; na++)
#pragma unroll
                for (int c = 0; c < 4; c++) acc[ma][na][c] = 0.0f;

#pragma unroll
        for (int ks = 0; ks < 8; ks++) {
            uint32_t af[2][4];
#pragma unroll
            for (int ma = 0; ma < 2; ma++) {
                const uint32_t row = (uint32_t)(ma * 16 + (l & 15));
                const uint32_t c16 = (uint32_t)(h * 16 + ks * 2 + (l >> 4));
                ldsm_x4(af[ma], bufg + row * 512u + ((c16 ^ (row & 7u)) << 4));
            }
#pragma unroll
            for (int ma = 0; ma < 2; ma++)
#pragma unroll
                for (int na = 0; na < 4; na++)
                    mma16816(acc[ma][na], af[ma], wreg[na][ks]);
        }

        // --- write ALL partials to scratch sub-region[h] (token-major,
        // chunk-swizzled; ~2-way worst case)
        {
            const uint32_t wr = scrp + (uint32_t)h * 4096u;
#pragma unroll
            for (int ma = 0; ma < 2; ma++) {
                const uint32_t r1 = (uint32_t)(ma * 16 + (l >> 2));
                const uint32_t r2 = r1 + 8u;
                const uint32_t hb = ((uint32_t)l & 1u) << 3;
#pragma unroll
                for (int na = 0; na < 4; na++) {
                    const uint32_t c = (uint32_t)(na * 2) + (((uint32_t)l & 3u) >> 1);
                    sts64f(wr + r1 * 128u + ((c ^ (r1 & 7u)) << 4) + hb,
                           acc[ma][na][0], acc[ma][na][1]);
                    sts64f(wr + r2 * 128u + ((c ^ (r2 & 7u)) << 4) + hb,
                           acc[ma][na][2], acc[ma][na][3]);
                }
            }
        }
        bar_pair(p + 1);

        // --- epilogue: this warp sums both halves for tokens [h*16, h*16+16),
        // tanh, coalesced STG.128 (8 lanes span one 128B token row; 4 rows/inst)
#pragma unroll
        for (int it = 0; it < 4; it++) {
            const int tk = h * 16 + it * 4 + (l >> 3);
            const uint32_t co = ((uint32_t)((l & 7) ^ (tk & 7))) << 4;
            float v0[4], v1[4];
            lds128f(v0, scrp + (uint32_t)tk * 128u + co);
            lds128f(v1, scrp + 4096u + (uint32_t)tk * 128u + co);
            float4 o;
            o.x = tanh_f(v0[0] + v1[0] + b4.x);
            o.y = tanh_f(v0[1] + v1[1] + b4.y);
            o.z = tanh_f(v0[2] + v1[2] + b4.z);
            o.w = tanh_f(v0[3] + v1[3] + b4.w);
            __stcs((float4*)&out[(size_t)(t * MT + tk) * HID + p * 32 + (l & 7) * 4], o);
        }
    }
}

// ----------------------------------------------------------------- launch ----

extern "C" void kernel_launch(void* const* d_in, const int* in_sizes, int n_in,
                              void* d_out, int out_size) {
    const float* x = (const float*)d_in[0];
    const float* W = (const float*)d_in[1];
    const float* b = (const float*)d_in[2];
    float* out = (float*)d_out;
    cudaFuncSetAttribute(rotor_kernel,
                         cudaFuncAttributeMaxDynamicSharedMemorySize, SMEM_TOTAL);
    rotor_kernel<<<GRID, NTHREADS, SMEM_TOTAL>>>(x, W, b, out);
}